// round 17
// baseline (speedup 1.0000x reference)
#include <cuda_runtime.h>
#include <cuda_bf16.h>
#include <cuda_fp16.h>
#include <math.h>
#include <stdint.h>

#define NBATCH 8
#define NNB    4096
#define NTOT   32768
#define EDG    65536
#define HID    512

// ---------------- scratch (device globals; no allocs allowed) ----------------
__device__ __half g_A[(size_t)NTOT * 1024];    // layer-2 A fp16: cols 0:512 H1, 512:1024 agg(H1), 64 MB
__device__ __half g_H2h[(size_t)NTOT * HID];   // head A (= H2) fp16, 32 MB
__device__ float g_hpart[(size_t)NTOT * 16];   // head partials [m][tile 0..3][4]
__device__ __half g_W2h[HID * 1024];           // stacked [W2_0; W2_1] transposed, fp16
__device__ __half g_Whh[HID * HID];            // Wh1 transposed, fp16
__device__ int   g_cnt[NNB];                   // zero at load; ends zero each launch (decrement scatter)
__device__ int   g_rowptr[NNB + 1];
__device__ int   g_csr_src[EDG];
__device__ float g_csr_norm[EDG];
__device__ float g_dinv[NNB];

// streams/events created at library load (before harness memory checkpoints)
struct StreamInit {
    cudaStream_t s2, s3, s4;
    cudaEvent_t evRoot, evW, evCSR, evE2, evE3, evE4;
    StreamInit() {
        cudaStreamCreateWithFlags(&s2, cudaStreamNonBlocking);
        cudaStreamCreateWithFlags(&s3, cudaStreamNonBlocking);
        cudaStreamCreateWithFlags(&s4, cudaStreamNonBlocking);
        cudaEventCreateWithFlags(&evRoot, cudaEventDisableTiming);
        cudaEventCreateWithFlags(&evW, cudaEventDisableTiming);
        cudaEventCreateWithFlags(&evCSR, cudaEventDisableTiming);
        cudaEventCreateWithFlags(&evE2, cudaEventDisableTiming);
        cudaEventCreateWithFlags(&evE3, cudaEventDisableTiming);
        cudaEventCreateWithFlags(&evE4, cudaEventDisableTiming);
    }
};
static StreamInit g_si;

__device__ __forceinline__ float siluf(float x) {
    return x / (1.0f + expf(-x));
}

__device__ __forceinline__ uint32_t pkh2(float a, float b) {
    return (uint32_t)__half_as_ushort(__float2half_rn(a)) |
           ((uint32_t)__half_as_ushort(__float2half_rn(b)) << 16);
}

// ---------------- PTX helpers ----------------
__device__ __forceinline__ uint32_t smem_u32(const void* p) {
    uint32_t a;
    asm("{ .reg .u64 t; cvta.to.shared.u64 t, %1; cvt.u32.u64 %0, t; }" : "=r"(a) : "l"(p));
    return a;
}

__device__ __forceinline__ void cp16(uint32_t dst, const void* src) {
    asm volatile("cp.async.cg.shared.global [%0], [%1], 16;" :: "r"(dst), "l"(src));
}
#define CP_COMMIT() asm volatile("cp.async.commit_group;" ::: "memory")
#define CP_WAIT(n)  asm volatile("cp.async.wait_group %0;" :: "n"(n) : "memory")

__device__ __forceinline__ void ldsm4(uint32_t* r, uint32_t addr) {
    asm volatile("ldmatrix.sync.aligned.m8n8.x4.shared.b16 {%0,%1,%2,%3}, [%4];"
                 : "=r"(r[0]), "=r"(r[1]), "=r"(r[2]), "=r"(r[3]) : "r"(addr));
}

__device__ __forceinline__ void mma_fp16(float* c, const uint32_t* a, uint32_t b0, uint32_t b1) {
    asm volatile(
        "mma.sync.aligned.m16n8k16.row.col.f32.f16.f16.f32 "
        "{%0,%1,%2,%3}, {%4,%5,%6,%7}, {%8,%9}, {%0,%1,%2,%3};"
        : "+f"(c[0]), "+f"(c[1]), "+f"(c[2]), "+f"(c[3])
        : "r"(a[0]), "r"(a[1]), "r"(a[2]), "r"(a[3]), "r"(b0), "r"(b1));
}

// ---------------- CSR build ----------------
__global__ void hist_kernel(const int* __restrict__ ei) {
    int e = blockIdx.x * blockDim.x + threadIdx.x;
    if (e < EDG) atomicAdd(&g_cnt[ei[EDG + e]], 1);
}

// exclusive scan of counts -> rowptr; dinv; LEAVES counts in g_cnt (scatter decrements to zero)
__global__ void scan_kernel() {
    __shared__ int s[1024];
    int tid = threadIdx.x;
    int c0 = g_cnt[tid * 4 + 0];
    int c1 = g_cnt[tid * 4 + 1];
    int c2 = g_cnt[tid * 4 + 2];
    int c3 = g_cnt[tid * 4 + 3];
    int local = c0 + c1 + c2 + c3;
    s[tid] = local;
    __syncthreads();
    for (int off = 1; off < 1024; off <<= 1) {
        int t = (tid >= off) ? s[tid - off] : 0;
        __syncthreads();
        s[tid] += t;
        __syncthreads();
    }
    int incl = s[tid];
    int excl = incl - local;
    g_rowptr[tid * 4 + 0] = excl;
    g_rowptr[tid * 4 + 1] = excl + c0;
    g_rowptr[tid * 4 + 2] = excl + c0 + c1;
    g_rowptr[tid * 4 + 3] = excl + c0 + c1 + c2;
    if (tid == 1023) g_rowptr[NNB] = incl;
    g_dinv[tid * 4 + 0] = rsqrtf((float)(c0 + 1));
    g_dinv[tid * 4 + 1] = rsqrtf((float)(c1 + 1));
    g_dinv[tid * 4 + 2] = rsqrtf((float)(c2 + 1));
    g_dinv[tid * 4 + 3] = rsqrtf((float)(c3 + 1));
}

__global__ void scatter_kernel(const int* __restrict__ ei) {
    int e = blockIdx.x * blockDim.x + threadIdx.x;
    if (e >= EDG) return;
    int s = ei[e];
    int d = ei[EDG + e];
    int c = atomicSub(&g_cnt[d], 1) - 1;   // count-1 .. 0; g_cnt ends at zero
    int pos = g_rowptr[d] + c;
    g_csr_src[pos]  = s;
    g_csr_norm[pos] = g_dinv[s] * g_dinv[d];
}

// ---------------- layer 1: fp16 H1 into g_A cols 0:512 (row partition via nbase) ----------------
__global__ void layer1_kernel(const float* __restrict__ X,
                              const float* __restrict__ W10, const float* __restrict__ b10,
                              const float* __restrict__ W11, const float* __restrict__ b11,
                              int nbase) {
    __shared__ float sW[5 * HID];
    int tid = threadIdx.x;
    for (int i = tid; i < HID; i += 256) {
        sW[i]           = W10[i];
        sW[HID + i]     = W10[HID + i];
        sW[2 * HID + i] = W11[i];
        sW[3 * HID + i] = W11[HID + i];
        sW[4 * HID + i] = b10[i] + b11[i];
    }
    __syncthreads();

    int warp = tid >> 5, lane = tid & 31;
    int n = nbase + blockIdx.x * 8 + warp;
    int v = n & (NNB - 1);
    int base = n & ~(NNB - 1);

    float x0 = X[2 * n], x1 = X[2 * n + 1];
    float a0 = 0.f, a1 = 0.f;
    int r0 = g_rowptr[v], r1 = g_rowptr[v + 1];
    for (int e = r0 + lane; e < r1; e += 32) {
        int s = g_csr_src[e];
        float nm = g_csr_norm[e];
        a0 += nm * X[2 * (base + s)];
        a1 += nm * X[2 * (base + s) + 1];
    }
#pragma unroll
    for (int off = 16; off; off >>= 1) {
        a0 += __shfl_down_sync(0xffffffffu, a0, off);
        a1 += __shfl_down_sync(0xffffffffu, a1, off);
    }
    a0 = __shfl_sync(0xffffffffu, a0, 0);
    a1 = __shfl_sync(0xffffffffu, a1, 0);
    float dv = g_dinv[v];
    float sn = dv * dv;
    a0 += sn * x0;
    a1 += sn * x1;

    __half* oh = &g_A[(size_t)n * 1024];
#pragma unroll 4
    for (int j = lane; j < HID; j += 32) {
        float h = x0 * sW[j] + x1 * sW[HID + j] + a0 * sW[2 * HID + j] + a1 * sW[3 * HID + j] + sW[4 * HID + j];
        oh[j] = __float2half_rn(siluf(h));
    }
}

// ---------------- aggregate H1 -> g_A cols 512:1024 (row partition via nbase) ----------------
// 256-thread block handles 4 nodes; 64 threads per node, 8 halves (16B) per thread
__global__ void aggH_kernel(int nbase) {
    int grp = threadIdx.x >> 6, lt = threadIdx.x & 63;
    int n = nbase + blockIdx.x * 4 + grp;
    int v = n & (NNB - 1);
    int base = n & ~(NNB - 1);
    int j = lt * 8;

    float acc[8] = {0.f, 0.f, 0.f, 0.f, 0.f, 0.f, 0.f, 0.f};
    int r0 = g_rowptr[v], r1 = g_rowptr[v + 1];
    for (int e = r0; e < r1; e++) {
        int s = g_csr_src[e];
        float nm = g_csr_norm[e];
        uint4 u = *(const uint4*)&g_A[(size_t)(base + s) * 1024 + j];
        float2 f0 = __half22float2(*(__half2*)&u.x);
        float2 f1 = __half22float2(*(__half2*)&u.y);
        float2 f2 = __half22float2(*(__half2*)&u.z);
        float2 f3 = __half22float2(*(__half2*)&u.w);
        acc[0] += nm * f0.x; acc[1] += nm * f0.y;
        acc[2] += nm * f1.x; acc[3] += nm * f1.y;
        acc[4] += nm * f2.x; acc[5] += nm * f2.y;
        acc[6] += nm * f3.x; acc[7] += nm * f3.y;
    }
    {
        float dv = g_dinv[v];
        float sn = dv * dv;
        uint4 u = *(const uint4*)&g_A[(size_t)n * 1024 + j];
        float2 f0 = __half22float2(*(__half2*)&u.x);
        float2 f1 = __half22float2(*(__half2*)&u.y);
        float2 f2 = __half22float2(*(__half2*)&u.z);
        float2 f3 = __half22float2(*(__half2*)&u.w);
        acc[0] += sn * f0.x; acc[1] += sn * f0.y;
        acc[2] += sn * f1.x; acc[3] += sn * f1.y;
        acc[4] += sn * f2.x; acc[5] += sn * f2.y;
        acc[6] += sn * f3.x; acc[7] += sn * f3.y;
    }
    uint4 o;
    o.x = pkh2(acc[0], acc[1]);
    o.y = pkh2(acc[2], acc[3]);
    o.z = pkh2(acc[4], acc[5]);
    o.w = pkh2(acc[6], acc[7]);
    *(uint4*)&g_A[(size_t)n * 1024 + 512 + j] = o;
}

// ---------------- transpose + convert ALL weights to fp16 (grid.z: 0=W20, 1=W21, 2=Wh1) ----------------
__global__ void conv_w_all_kernel(const float* __restrict__ W20, const float* __restrict__ W21,
                                  const float* __restrict__ Wh1) {
    __shared__ float tile[32][33];
    const float* W;
    __half* T;
    int ldT, koff;
    if (blockIdx.z == 0)      { W = W20; T = g_W2h; ldT = 1024; koff = 0; }
    else if (blockIdx.z == 1) { W = W21; T = g_W2h; ldT = 1024; koff = 512; }
    else                      { W = Wh1; T = g_Whh; ldT = 512;  koff = 0; }

    int bn = blockIdx.x * 32, bk = blockIdx.y * 32;
    int tx = threadIdx.x;
    for (int ty = threadIdx.y; ty < 32; ty += 8)
        tile[ty][tx] = W[(size_t)(bk + ty) * HID + bn + tx];
    __syncthreads();
    for (int ty = threadIdx.y; ty < 32; ty += 8) {
        float x = tile[tx][ty];
        size_t o = (size_t)(bn + ty) * ldT + koff + bk + tx;
        T[o] = __float2half_rn(x);
    }
}

// ---------------- fp16 HMMA GEMM, 8 warps x (64x32) tiles, 3-stage cp.async ----------------
// Single __syncthreads per K-iteration (barrier both publishes stage t and frees stage (t+2)%3).
// C = A(fp16) @ B(fp16)^T, fp32 accum.  mbase: row offset of this launch's m-partition.
// MODE 2: Ch = fp16(silu(acc + bias1 + bias2))
// MODE 1: head projection: silu(acc+bias1) @ Wh2-tile -> partials Cf[m][bx][4]
#define TROW_B   80
#define TILE_B   (128 * TROW_B)          // 10240
#define STAGE_B  (2 * TILE_B)            // 20480: A, B
#define NSTAGE   3
#define SWH2_OFF (NSTAGE * STAGE_B)      // 61440, 2KB: Wh2 tile [128][4]
#define SPART_OFF (SWH2_OFF + 2048)      // 63488, 8KB: s_part[128][4 slots][4]
#define GEMM_SMEM_2 (NSTAGE * STAGE_B)           // 61440
#define GEMM_SMEM_1 (SPART_OFF + 8192)           // 71680

__device__ __forceinline__ void load_stage(uint32_t sb, uint32_t stg,
                                           const __half* A, const __half* B,
                                           int m0, int n0, int kc, int lda, int ldb, int tid) {
#pragma unroll
    for (int i = 0; i < 2; i++) {
        int idx = tid + i * 256;
        int r = idx >> 2, g = idx & 3;
        uint32_t doff = stg + (uint32_t)(r * TROW_B + g * 16);
        cp16(sb + doff,          A + (size_t)(m0 + r) * lda + kc + g * 8);
        cp16(sb + doff + TILE_B, B + (size_t)(n0 + r) * ldb + kc + g * 8);
    }
}

template <int MODE>
__global__ void __launch_bounds__(256, 2)
hmma_gemm_kernel(const __half* __restrict__ A, const __half* __restrict__ B,
                 float* __restrict__ Cf, __half* __restrict__ Ch,
                 const float* __restrict__ bias1, const float* __restrict__ bias2,
                 const float* __restrict__ Wproj,
                 int lda, int ldb, int ldc, int K, int mbase) {
    extern __shared__ __align__(128) char smem[];
    uint32_t sb = smem_u32(smem);
    int tid = threadIdx.x, wid = tid >> 5, lane = tid & 31;
    int n0 = blockIdx.x * 128;
    int m0 = mbase + blockIdx.y * 128;
    int wm = (wid & 1) * 64;
    int wn = (wid >> 1) * 32;

    float acc[4][4][4];
#pragma unroll
    for (int i = 0; i < 4; i++)
#pragma unroll
        for (int j = 0; j < 4; j++)
#pragma unroll
            for (int q = 0; q < 4; q++) acc[i][j][q] = 0.f;

    int lrow = lane & 15;
    uint32_t kByte = (uint32_t)(lane >> 4) * 16;
    uint32_t aRow[4], bRow[2];
#pragma unroll
    for (int i = 0; i < 4; i++) aRow[i] = (uint32_t)((wm + i * 16 + lrow) * TROW_B) + kByte;
#pragma unroll
    for (int p = 0; p < 2; p++) bRow[p] = (uint32_t)((wn + p * 16 + lrow) * TROW_B) + kByte;

    const int nt = K / 32;

    load_stage(sb, 0, A, B, m0, n0, 0, lda, ldb, tid);
    CP_COMMIT();
    load_stage(sb, STAGE_B, A, B, m0, n0, 32, lda, ldb, tid);
    CP_COMMIT();

    for (int t = 0; t < nt; t++) {
        if (t + 1 < nt) {
            CP_WAIT(1);
        } else {
            CP_WAIT(0);
        }
        __syncthreads();
        if (t + 2 < nt) {
            load_stage(sb, (uint32_t)((t + 2) % NSTAGE) * STAGE_B, A, B, m0, n0,
                       (t + 2) * 32, lda, ldb, tid);
            CP_COMMIT();
        }

        uint32_t stg = (uint32_t)(t % NSTAGE) * STAGE_B;
        uint32_t aB = sb + stg;
        uint32_t bB = aB + TILE_B;

#pragma unroll
        for (int kk = 0; kk < 2; kk++) {
            uint32_t ko = (uint32_t)kk * 32;
            uint32_t ah[4][4], bh[2][4];
#pragma unroll
            for (int i = 0; i < 4; i++) ldsm4(ah[i], aB + aRow[i] + ko);
#pragma unroll
            for (int p = 0; p < 2; p++) ldsm4(bh[p], bB + bRow[p] + ko);
#pragma unroll
            for (int i = 0; i < 4; i++)
#pragma unroll
                for (int p = 0; p < 2; p++) {
                    mma_fp16(acc[i][2 * p],     ah[i], bh[p][0], bh[p][2]);
                    mma_fp16(acc[i][2 * p + 1], ah[i], bh[p][1], bh[p][3]);
                }
        }
    }

    int quad = lane >> 2, tq = lane & 3;

    if (MODE == 2) {
#pragma unroll
        for (int i = 0; i < 4; i++) {
            int row = m0 + wm + i * 16 + quad;
#pragma unroll
            for (int j = 0; j < 4; j++) {
                int col = n0 + wn + j * 8 + tq * 2;
                float bb0 = bias1[col] + bias2[col];
                float bb1 = bias1[col + 1] + bias2[col + 1];
                float v00 = siluf(acc[i][j][0] + bb0);
                float v01 = siluf(acc[i][j][1] + bb1);
                float v10 = siluf(acc[i][j][2] + bb0);
                float v11 = siluf(acc[i][j][3] + bb1);
                *(uint32_t*)&Ch[(size_t)row * ldc + col]       = pkh2(v00, v01);
                *(uint32_t*)&Ch[(size_t)(row + 8) * ldc + col] = pkh2(v10, v11);
            }
        }
    } else {
        // MODE 1: fused head projection.
        float4* sWh2 = (float4*)(smem + SWH2_OFF);
        float*  sPart = (float*)(smem + SPART_OFF);  // [128 rows][4 slots][4]
        __syncthreads();  // all compute done before repurposing smem
        if (tid < 128) sWh2[tid] = ((const float4*)Wproj)[n0 + tid];
        __syncthreads();

        int slot = wid >> 1;
#pragma unroll
        for (int i = 0; i < 4; i++) {
            float p0[4] = {0.f, 0.f, 0.f, 0.f};
            float p1[4] = {0.f, 0.f, 0.f, 0.f};
#pragma unroll
            for (int j = 0; j < 4; j++) {
                int c = wn + j * 8 + tq * 2;
                float bb0 = bias1[n0 + c], bb1 = bias1[n0 + c + 1];
                float v00 = siluf(acc[i][j][0] + bb0);
                float v01 = siluf(acc[i][j][1] + bb1);
                float v10 = siluf(acc[i][j][2] + bb0);
                float v11 = siluf(acc[i][j][3] + bb1);
                float4 w0 = sWh2[c], w1 = sWh2[c + 1];
                p0[0] += v00 * w0.x + v01 * w1.x;
                p0[1] += v00 * w0.y + v01 * w1.y;
                p0[2] += v00 * w0.z + v01 * w1.z;
                p0[3] += v00 * w0.w + v01 * w1.w;
                p1[0] += v10 * w0.x + v11 * w1.x;
                p1[1] += v10 * w0.y + v11 * w1.y;
                p1[2] += v10 * w0.z + v11 * w1.z;
                p1[3] += v10 * w0.w + v11 * w1.w;
            }
#pragma unroll
            for (int k = 0; k < 4; k++) {
                p0[k] += __shfl_xor_sync(0xffffffffu, p0[k], 1);
                p0[k] += __shfl_xor_sync(0xffffffffu, p0[k], 2);
                p1[k] += __shfl_xor_sync(0xffffffffu, p1[k], 1);
                p1[k] += __shfl_xor_sync(0xffffffffu, p1[k], 2);
            }
            if (tq == 0) {
                int r = wm + i * 16 + quad;
#pragma unroll
                for (int k = 0; k < 4; k++) {
                    sPart[(r * 4 + slot) * 4 + k]       = p0[k];
                    sPart[((r + 8) * 4 + slot) * 4 + k] = p1[k];
                }
            }
        }
        __syncthreads();
        if (tid < 128) {
            float4 s = make_float4(0.f, 0.f, 0.f, 0.f);
#pragma unroll
            for (int sl = 0; sl < 4; sl++) {
                float4 v = *(float4*)&sPart[(tid * 4 + sl) * 4];
                s.x += v.x; s.y += v.y; s.z += v.z; s.w += v.w;
            }
            ((float4*)Cf)[(size_t)(m0 + tid) * 4 + blockIdx.x] = s;
        }
    }
}

// ---------------- finish: sum head partials, tanh/store ----------------
__global__ void finish_kernel(const float* __restrict__ hp, const float* __restrict__ bh2,
                              float* __restrict__ out, int nbase) {
    int n = nbase + blockIdx.x * 256 + threadIdx.x;
    const float4* v = (const float4*)hp + (size_t)n * 4;
    float4 a = v[0], b = v[1], c = v[2], d = v[3];
    float o0 = a.x + b.x + c.x + d.x + bh2[0];
    float o1 = a.y + b.y + c.y + d.y + bh2[1];
    float o2 = a.z + b.z + c.z + d.z + bh2[2];
    float o3 = a.w + b.w + c.w + d.w + bh2[3];
    out[2 * n + 0] = tanhf(o0);
    out[2 * n + 1] = tanhf(o1);
    out[2 * NTOT + 2 * n + 0] = o2;
    out[2 * NTOT + 2 * n + 1] = o3;
}

// ---------------- host ----------------
extern "C" void kernel_launch(void* const* d_in, const int* in_sizes, int n_in,
                              void* d_out, int out_size) {
    const float* X   = (const float*)d_in[0];
    const int*   EI  = (const int*)d_in[1];
    const float* W10 = (const float*)d_in[2];
    const float* b10 = (const float*)d_in[3];
    const float* W11 = (const float*)d_in[4];
    const float* b11 = (const float*)d_in[5];
    const float* W20 = (const float*)d_in[6];
    const float* b20 = (const float*)d_in[7];
    const float* W21 = (const float*)d_in[8];
    const float* b21 = (const float*)d_in[9];
    const float* Wh1 = (const float*)d_in[10];
    const float* bh1 = (const float*)d_in[11];
    const float* Wh2 = (const float*)d_in[12];
    const float* bh2 = (const float*)d_in[13];
    float* out = (float*)d_out;

    __half *pA, *pH2h, *pW2h, *pWhh;
    float* pHp;
    cudaGetSymbolAddress((void**)&pA,   g_A);
    cudaGetSymbolAddress((void**)&pH2h, g_H2h);
    cudaGetSymbolAddress((void**)&pW2h, g_W2h);
    cudaGetSymbolAddress((void**)&pWhh, g_Whh);
    cudaGetSymbolAddress((void**)&pHp,  g_hpart);

    cudaFuncSetAttribute(hmma_gemm_kernel<2>, cudaFuncAttributeMaxDynamicSharedMemorySize, GEMM_SMEM_2);
    cudaFuncSetAttribute(hmma_gemm_kernel<1>, cudaFuncAttributeMaxDynamicSharedMemorySize, GEMM_SMEM_1);

    const int QTR = NTOT / 4;    // 2 batches per quarter (batch-closed row partition)
    dim3 gq(4, QTR / 128);

    cudaStream_t qs[4] = {(cudaStream_t)0, g_si.s2, g_si.s3, g_si.s4};

    // root fan-out
    cudaEventRecord(g_si.evRoot, 0);
    cudaStreamWaitEvent(g_si.s2, g_si.evRoot, 0);
    cudaStreamWaitEvent(g_si.s3, g_si.evRoot, 0);
    cudaStreamWaitEvent(g_si.s4, g_si.evRoot, 0);

    // s2: weight conversion (independent of CSR)
    dim3 wb(32, 8), wg(16, 16, 3);
    conv_w_all_kernel<<<wg, wb, 0, g_si.s2>>>(W20, W21, Wh1);
    cudaEventRecord(g_si.evW, g_si.s2);

    // stream0: CSR chain
    hist_kernel<<<EDG / 256, 256>>>(EI);
    scan_kernel<<<1, 1024>>>();
    scatter_kernel<<<EDG / 256, 256>>>(EI);
    cudaEventRecord(g_si.evCSR, 0);

    // per-quarter pipelines
    for (int q = 0; q < 4; q++) {
        cudaStream_t s = qs[q];
        int nb = q * QTR;
        if (q != 0) cudaStreamWaitEvent(s, g_si.evCSR, 0);  // q0 is in-stream after CSR
        layer1_kernel<<<QTR / 8, 256, 0, s>>>(X, W10, b10, W11, b11, nb);
        aggH_kernel<<<QTR / 4, 256, 0, s>>>(nb);
        if (q != 1) cudaStreamWaitEvent(s, g_si.evW, 0);    // q1 (s2) has conv_w in-stream
        hmma_gemm_kernel<2><<<gq, 256, GEMM_SMEM_2, s>>>(
            pA, pW2h, nullptr, pH2h, b20, b21, nullptr,
            1024, 1024, 512, 1024, nb);
        hmma_gemm_kernel<1><<<gq, 256, GEMM_SMEM_1, s>>>(
            pH2h, pWhh, pHp, nullptr, bh1, nullptr, Wh2,
            512, 512, 512, 512, nb);
        finish_kernel<<<QTR / 256, 256, 0, s>>>(pHp, bh2, out, nb);
    }

    // join side streams back into the capture's origin stream
    cudaEventRecord(g_si.evE2, g_si.s2);
    cudaEventRecord(g_si.evE3, g_si.s3);
    cudaEventRecord(g_si.evE4, g_si.s4);
    cudaStreamWaitEvent(0, g_si.evE2, 0);
    cudaStreamWaitEvent(0, g_si.evE3, 0);
    cudaStreamWaitEvent(0, g_si.evE4, 0);
}